// round 6
// baseline (speedup 1.0000x reference)
#include <cuda_runtime.h>
#include <cuda_fp16.h>
#include <cstdint>

#define N_NODES 10000
#define N_EDGES 640000
#define HID 128
#define N_GRAPHS 64

// ---------------- device scratch (no dynamic alloc allowed) ----------------
__device__ int    g_deg[N_NODES];
__device__ float  g_dis[N_NODES];
__device__ int    g_rowptr[N_NODES + 1];
__device__ int    g_pos[N_EDGES];          // slot of edge within its dst row
__device__ int    g_col[N_EDGES];          // src ids grouped by dst (CSR)
__device__ __half g_hs[N_NODES * HID];     // fp16: (X @ W) * dis[row]
__device__ __half g_xb16[N_NODES * HID];   // fp16 hidden activations
__device__ float  g_xb[N_NODES * HID];     // fp32 final-layer activations
__device__ __half g_w16[3 * HID * HID];    // fp16 weights

// ---------------- cp.async helpers ----------------
__device__ __forceinline__ void cp16(void* smem_dst, const void* gsrc) {
    uint32_t s = (uint32_t)__cvta_generic_to_shared(smem_dst);
    asm volatile("cp.async.cg.shared.global [%0], [%1], 16;" :: "r"(s), "l"(gsrc));
}
__device__ __forceinline__ void cp_commit() {
    asm volatile("cp.async.commit_group;" ::: "memory");
}
__device__ __forceinline__ void cp_wait0() {
    asm volatile("cp.async.wait_group 0;" ::: "memory");
}

// ---------------- convert the 3 weight matrices to fp16 (once) ----------------
__global__ __launch_bounds__(256) void convw_kernel(const float* __restrict__ W0,
                                                    const float* __restrict__ W1,
                                                    const float* __restrict__ W2) {
    int id = blockIdx.x * blockDim.x + threadIdx.x;   // 0 .. 3*4096-1 (float4 units)
    int m = id / 4096;
    int off = (id % 4096) * 4;
    const float* W = (m == 0) ? W0 : (m == 1) ? W1 : W2;
    float4 v = *(const float4*)&W[off];
    __half2 h0 = __floats2half2_rn(v.x, v.y);
    __half2 h1 = __floats2half2_rn(v.z, v.w);
    *(__half2*)&g_w16[m * HID * HID + off + 0] = h0;
    *(__half2*)&g_w16[m * HID * HID + off + 2] = h1;
}

// ---------------- degree histogram over dst; record slot per edge ----------
__global__ __launch_bounds__(256) void pos_kernel(const int* __restrict__ dst) {
    int base = (blockIdx.x * blockDim.x + threadIdx.x) * 4;
    if (base + 3 < N_EDGES) {
        int d0 = dst[base + 0];
        int d1 = dst[base + 1];
        int d2 = dst[base + 2];
        int d3 = dst[base + 3];
        g_pos[base + 0] = atomicAdd(&g_deg[d0], 1);
        g_pos[base + 1] = atomicAdd(&g_deg[d1], 1);
        g_pos[base + 2] = atomicAdd(&g_deg[d2], 1);
        g_pos[base + 3] = atomicAdd(&g_deg[d3], 1);
    } else {
        for (int e = base; e < N_EDGES; e++)
            g_pos[e] = atomicAdd(&g_deg[dst[e]], 1);
    }
}

// ---------------- single-block scan: rowptr, dis ----------------
__global__ void scan_kernel() {
    __shared__ int ps[1024];
    const int C = 10;  // 1024 * 10 >= N_NODES
    int tid = threadIdx.x;
    int start = tid * C;
    int sum = 0;
#pragma unroll
    for (int i = 0; i < C; i++) {
        int idx = start + i;
        if (idx < N_NODES) sum += g_deg[idx];
    }
    ps[tid] = sum;
    __syncthreads();
    for (int off = 1; off < 1024; off <<= 1) {
        int v = (tid >= off) ? ps[tid - off] : 0;
        __syncthreads();
        ps[tid] += v;
        __syncthreads();
    }
    int run = (tid == 0) ? 0 : ps[tid - 1];
#pragma unroll
    for (int i = 0; i < C; i++) {
        int idx = start + i;
        if (idx < N_NODES) {
            int d = g_deg[idx];
            g_rowptr[idx] = run;
            g_dis[idx] = rsqrtf((float)(d + 1));
            run += d;
        }
    }
    if (tid == 1023) g_rowptr[N_NODES] = ps[1023];
}

// ---------------- CSR fill: pure scatter, no atomics ----------------
__global__ __launch_bounds__(256) void fill_kernel(const int* __restrict__ src,
                                                   const int* __restrict__ dst) {
    int base = (blockIdx.x * blockDim.x + threadIdx.x) * 4;
    if (base + 3 < N_EDGES) {
        int d0 = dst[base + 0], d1 = dst[base + 1];
        int d2 = dst[base + 2], d3 = dst[base + 3];
        int p0 = g_rowptr[d0] + g_pos[base + 0];
        int p1 = g_rowptr[d1] + g_pos[base + 1];
        int p2 = g_rowptr[d2] + g_pos[base + 2];
        int p3 = g_rowptr[d3] + g_pos[base + 3];
        g_col[p0] = src[base + 0];
        g_col[p1] = src[base + 1];
        g_col[p2] = src[base + 2];
        g_col[p3] = src[base + 3];
    } else {
        for (int e = base; e < N_EDGES; e++)
            g_col[g_rowptr[dst[e]] + g_pos[e]] = src[e];
    }
}

// ---------------- fp16 tensor-core GEMM ----------------
// H[r][c] = half( (sum_k X[r][k]*W16[k][c]) * dis[r] )
// TBM=32 rows/block, N=128, K=128. W16 fp16 staged via cp.async.
// 256 threads = 8 warps: 2 in M (16 rows), 4 in N (32 cols).
#define TBM 32
#define SMH 136    // half-stride; row pitch 272B (16B aligned, conflict-free ldmatrix)
#define GEMM_SMEM_BYTES ((TBM + 128) * SMH * 2)

template <typename TA>
__global__ __launch_bounds__(256) void gemm_kernel(const TA* __restrict__ X,
                                                   const __half* __restrict__ W16,
                                                   __half* __restrict__ H, int M) {
    extern __shared__ __half smh[];
    __half* Xs = smh;              // [TBM][SMH]
    __half* Ws = smh + TBM * SMH;  // [128][SMH], layout [k][n]
    int tid = threadIdx.x;
    int lane = tid & 31;
    int wid = tid >> 5;
    int rb = blockIdx.x * TBM;

    // ---- stage W fp16 via cp.async: 128 rows x 16 uint4 ----
#pragma unroll
    for (int u = 0; u < 8; u++) {
        int id = tid + u * 256;        // 2048 uint4 slots
        int r = id >> 4;
        int c8 = (id & 15) * 8;
        cp16(&Ws[r * SMH + c8], &W16[r * HID + c8]);
    }
    cp_commit();

    // ---- stage X ----
    if constexpr (sizeof(TA) == 4) {
        // fp32 input: 32 rows x 32 float4 = 1024 slots
#pragma unroll
        for (int u = 0; u < 4; u++) {
            int id = tid + u * 256;
            int r = id >> 5;
            int c4 = (id & 31) * 4;
            float4 v = make_float4(0.f, 0.f, 0.f, 0.f);
            if (rb + r < M) v = *(const float4*)&((const float*)X)[(rb + r) * HID + c4];
            *(__half2*)&Xs[r * SMH + c4 + 0] = __floats2half2_rn(v.x, v.y);
            *(__half2*)&Xs[r * SMH + c4 + 2] = __floats2half2_rn(v.z, v.w);
        }
    } else {
        // fp16 input: 32 rows x 16 uint4 = 512 slots
#pragma unroll
        for (int u = 0; u < 2; u++) {
            int id = tid + u * 256;
            int r = id >> 4;
            int c8 = (id & 15) * 8;
            uint4 v = make_uint4(0, 0, 0, 0);
            if (rb + r < M) v = *(const uint4*)&((const __half*)X)[(rb + r) * HID + c8];
            *(uint4*)&Xs[r * SMH + c8] = v;
        }
    }
    cp_wait0();
    __syncthreads();

    int gid = lane >> 2;     // 0..7
    int tig = lane & 3;      // 0..3
    int wm = wid & 1;        // M-slab (16 rows)
    int wn = wid >> 1;       // N-quarter (32 cols)
    int tr = lane & 7;       // ldmatrix row-in-tile
    int tt = lane >> 3;      // ldmatrix tile id

    uint32_t xs_base = (uint32_t)__cvta_generic_to_shared(Xs);
    uint32_t ws_base = (uint32_t)__cvta_generic_to_shared(Ws);
    uint32_t a_addr0 = xs_base +
        (((wm * 16 + (tt & 1) * 8 + tr) * SMH + (tt >> 1) * 8) << 1);
    uint32_t b_addr0 = ws_base +
        ((((tt & 1) * 8 + tr) * SMH + wn * 32 + (tt >> 1) * 8) << 1);

    float d0[4], d1[4], d2[4], d3[4];
#pragma unroll
    for (int t = 0; t < 4; t++) { d0[t] = d1[t] = d2[t] = d3[t] = 0.f; }

#pragma unroll
    for (int k0 = 0; k0 < 128; k0 += 16) {
        uint32_t a0, a1, a2, a3;
        asm volatile("ldmatrix.sync.aligned.m8n8.x4.shared.b16 {%0,%1,%2,%3}, [%4];"
                     : "=r"(a0), "=r"(a1), "=r"(a2), "=r"(a3)
                     : "r"(a_addr0 + (k0 << 1)));
#pragma unroll
        for (int p = 0; p < 2; p++) {
            uint32_t b0a, b1a, b0b, b1b;
            asm volatile("ldmatrix.sync.aligned.m8n8.x4.trans.shared.b16 {%0,%1,%2,%3}, [%4];"
                         : "=r"(b0a), "=r"(b1a), "=r"(b0b), "=r"(b1b)
                         : "r"(b_addr0 + ((k0 * SMH + p * 16) << 1)));
            int t0 = 2 * p;
            int t1 = 2 * p + 1;
            asm volatile(
                "mma.sync.aligned.m16n8k16.row.col.f32.f16.f16.f32 "
                "{%0,%1,%2,%3}, {%4,%5,%6,%7}, {%8,%9}, {%0,%1,%2,%3};\n"
                : "+f"(d0[t0]), "+f"(d1[t0]), "+f"(d2[t0]), "+f"(d3[t0])
                : "r"(a0), "r"(a1), "r"(a2), "r"(a3), "r"(b0a), "r"(b1a));
            asm volatile(
                "mma.sync.aligned.m16n8k16.row.col.f32.f16.f16.f32 "
                "{%0,%1,%2,%3}, {%4,%5,%6,%7}, {%8,%9}, {%0,%1,%2,%3};\n"
                : "+f"(d0[t1]), "+f"(d1[t1]), "+f"(d2[t1]), "+f"(d3[t1])
                : "r"(a0), "r"(a1), "r"(a2), "r"(a3), "r"(b0b), "r"(b1b));
        }
    }

    // ---- epilogue: scale by dis[row], convert to fp16, store ----
    int arow = wm * 16 + gid;
    int ncol = wn * 32;
    int r0 = rb + arow;
    int r1 = r0 + 8;
    float dis0 = (r0 < M) ? g_dis[r0] : 0.f;
    float dis1 = (r1 < M) ? g_dis[r1] : 0.f;
#pragma unroll
    for (int t = 0; t < 4; t++) {
        int c = ncol + t * 8 + tig * 2;
        if (r0 < M)
            *(__half2*)&H[r0 * HID + c] = __floats2half2_rn(d0[t] * dis0, d1[t] * dis0);
        if (r1 < M)
            *(__half2*)&H[r1 * HID + c] = __floats2half2_rn(d2[t] * dis1, d3[t] * dis1);
    }
}

// ---------------- aggregation: warp per node, fp16 CSR gather ----------------
// out[i] = dis[i] * (hs[i] + sum_{e: dst=i} hs[src_e]) + b ; relu iff fp16 out
template <typename TO>
__global__ __launch_bounds__(256) void agg_kernel(const __half* __restrict__ HS_,
                                                  const float* __restrict__ bias,
                                                  TO* __restrict__ OUT, int relu) {
    const uint2* HS = (const uint2*)HS_;   // 32 uint2 (8B) per 128-half row
    int warp = (blockIdx.x * blockDim.x + threadIdx.x) >> 5;
    int lane = threadIdx.x & 31;
    if (warp >= N_NODES) return;
    int e0 = g_rowptr[warp];
    int e1 = g_rowptr[warp + 1];

    float4 acc;
    {   // self-loop term
        uint2 sv = HS[warp * 32 + lane];
        float2 f0 = __half22float2(*(__half2*)&sv.x);
        float2 f1 = __half22float2(*(__half2*)&sv.y);
        acc.x = f0.x; acc.y = f0.y; acc.z = f1.x; acc.w = f1.y;
    }

    int base = e0;
    for (; base + 32 <= e1; base += 32) {
        int s = g_col[base + lane];
#pragma unroll
        for (int jj = 0; jj < 4; jj++) {
            uint2 v[8];
#pragma unroll
            for (int j2 = 0; j2 < 8; j2++) {
                int ss = __shfl_sync(0xffffffffu, s, jj * 8 + j2);
                v[j2] = HS[ss * 32 + lane];
            }
#pragma unroll
            for (int j2 = 0; j2 < 8; j2++) {
                float2 f0 = __half22float2(*(__half2*)&v[j2].x);
                float2 f1 = __half22float2(*(__half2*)&v[j2].y);
                acc.x += f0.x; acc.y += f0.y; acc.z += f1.x; acc.w += f1.y;
            }
        }
    }
    int rem = e1 - base;
    if (rem > 0) {
        int s = (lane < rem) ? g_col[base + lane] : 0;
        for (int j = 0; j < rem; j++) {
            int ss = __shfl_sync(0xffffffffu, s, j);
            uint2 v = HS[ss * 32 + lane];
            float2 f0 = __half22float2(*(__half2*)&v.x);
            float2 f1 = __half22float2(*(__half2*)&v.y);
            acc.x += f0.x; acc.y += f0.y; acc.z += f1.x; acc.w += f1.y;
        }
    }

    float d = g_dis[warp];
    float4 bb = *(const float4*)&bias[lane * 4];
    float4 o;
    o.x = acc.x * d + bb.x;
    o.y = acc.y * d + bb.y;
    o.z = acc.z * d + bb.z;
    o.w = acc.w * d + bb.w;
    if (relu) {
        o.x = fmaxf(o.x, 0.f); o.y = fmaxf(o.y, 0.f);
        o.z = fmaxf(o.z, 0.f); o.w = fmaxf(o.w, 0.f);
    }
    if constexpr (sizeof(TO) == 2) {
        uint2 pk;
        *(__half2*)&pk.x = __floats2half2_rn(o.x, o.y);
        *(__half2*)&pk.y = __floats2half2_rn(o.z, o.w);
        ((uint2*)OUT)[warp * 32 + lane] = pk;
    } else {
        *(float4*)&((float*)OUT)[warp * HID + lane * 4] = o;
    }
}

// ---------------- mean pool: batch is sorted -> segment sums, no atomics ----------
__device__ __forceinline__ int lower_bound_dev(const int* __restrict__ a, int n, int key) {
    int lo = 0, hi = n;
    while (lo < hi) {
        int mid = (lo + hi) >> 1;
        if (a[mid] < key) lo = mid + 1; else hi = mid;
    }
    return lo;
}

__global__ __launch_bounds__(256) void pool_kernel(const float* __restrict__ H,
                                                   const int* __restrict__ batch,
                                                   float* __restrict__ out) {
    int g = blockIdx.x;
    int t = threadIdx.x;          // 256 threads: 2 row-halves x 128 cols
    int lo = lower_bound_dev(batch, N_NODES, g);
    int hi = lower_bound_dev(batch, N_NODES, g + 1);
    int c = t & 127;
    int half = t >> 7;
    float sum = 0.0f;
    int r = lo + half;
    for (; r + 6 < hi; r += 8) {
        float v0 = H[(r + 0) * HID + c];
        float v1 = H[(r + 2) * HID + c];
        float v2 = H[(r + 4) * HID + c];
        float v3 = H[(r + 6) * HID + c];
        sum += v0 + v1 + v2 + v3;
    }
    for (; r < hi; r += 2) sum += H[r * HID + c];
    __shared__ float red[256];
    red[t] = sum;
    __syncthreads();
    if (t < 128) {
        float tot = red[t] + red[t + 128];
        int n = hi - lo;
        out[g * HID + t] = tot / (float)max(n, 1);
    }
}

// ---------------- launch ----------------
extern "C" void kernel_launch(void* const* d_in, const int* in_sizes, int n_in,
                              void* d_out, int out_size) {
    const float* x     = (const float*)d_in[0];
    const int*   eidx  = (const int*)d_in[1];
    const int*   batch = (const int*)d_in[2];
    const float* W0    = (const float*)d_in[3];
    const float* b0    = (const float*)d_in[4];
    const float* W1    = (const float*)d_in[5];
    const float* b1    = (const float*)d_in[6];
    const float* W2    = (const float*)d_in[7];
    const float* b2    = (const float*)d_in[8];
    float* out = (float*)d_out;

    const int* src = eidx;
    const int* dst = eidx + N_EDGES;

    __half* hs = nullptr;
    __half* xb16 = nullptr;
    float* xb = nullptr;
    int* degp = nullptr;
    __half* w16 = nullptr;
    cudaGetSymbolAddress((void**)&hs, g_hs);
    cudaGetSymbolAddress((void**)&xb16, g_xb16);
    cudaGetSymbolAddress((void**)&xb, g_xb);
    cudaGetSymbolAddress((void**)&degp, g_deg);
    cudaGetSymbolAddress((void**)&w16, g_w16);

    static bool attr_set = false;
    if (!attr_set) {
        cudaFuncSetAttribute(gemm_kernel<float>,
                             cudaFuncAttributeMaxDynamicSharedMemorySize,
                             GEMM_SMEM_BYTES);
        cudaFuncSetAttribute(gemm_kernel<__half>,
                             cudaFuncAttributeMaxDynamicSharedMemorySize,
                             GEMM_SMEM_BYTES);
        attr_set = true;
    }

    cudaMemsetAsync(degp, 0, N_NODES * sizeof(int));

    convw_kernel<<<48, 256>>>(W0, W1, W2);
    int e4_grid = (N_EDGES / 4 + 255) / 256;
    pos_kernel<<<e4_grid, 256>>>(dst);
    scan_kernel<<<1, 1024>>>();
    fill_kernel<<<e4_grid, 256>>>(src, dst);

    int gemm_grid = (N_NODES + TBM - 1) / TBM;   // 313
    int agg_grid = (N_NODES + 7) / 8;            // 8 warps per 256-thread block

    // layer 0 (fp32 input)
    gemm_kernel<float><<<gemm_grid, 256, GEMM_SMEM_BYTES>>>(x, w16, hs, N_NODES);
    agg_kernel<__half><<<agg_grid, 256>>>(hs, b0, xb16, 1);
    // layer 1 (fp16 input)
    gemm_kernel<__half><<<gemm_grid, 256, GEMM_SMEM_BYTES>>>(xb16, w16 + HID * HID, hs, N_NODES);
    agg_kernel<__half><<<agg_grid, 256>>>(hs, b1, xb16, 1);
    // layer 2 (fp16 input, fp32 output for pool)
    gemm_kernel<__half><<<gemm_grid, 256, GEMM_SMEM_BYTES>>>(xb16, w16 + 2 * HID * HID, hs, N_NODES);
    agg_kernel<float><<<agg_grid, 256>>>(hs, b2, xb, 0);

    pool_kernel<<<N_GRAPHS, 256>>>(xb, batch, out);
}